// round 14
// baseline (speedup 1.0000x reference)
#include <cuda_runtime.h>
#include <math.h>

#define BB 8
#define NN 1000
#define CC 81
#define FG 80           // foreground classes
#define KK 100
#define MSZ 28
#define NPROB (BB*FG)   // 640
#define IMG_W 1216.0f
#define IMG_H 800.0f
#define SCORE_TH 0.05f
#define NMS_TH 0.5f
#define CLIPV 4.135166556742356f   // log(1000/16)
#define CAP 4096
#define NB 1024         // select histogram bins
#define CB 512          // collect buffer cap
#define BIN_BASE 0x3D4C // float bits top-16 of 0.05
#define GRID NPROB      // 640 blocks for fused softmax+nms
#define THR 256

// ---- scratch (no allocations allowed) ----
__device__ int                g_cnt[NPROB];          // candidates per (b,c)
__device__ int                g_kcnt[NPROB];         // kept after NMS per (b,c)
__device__ float              g_score[NPROB*NN];
__device__ float              g_box[NPROB*NN*4];
__device__ unsigned           g_nidx[NPROB*NN];
__device__ unsigned long long g_keys[NPROB*NN];      // compacted kept keys
__device__ int                g_labels[BB*KK];
__device__ unsigned           g_arrive;              // barrier arrive counter
__device__ unsigned           g_gen;                 // barrier generation

// software grid barrier — all GRID blocks resident (proof: 36.3KB smem -> 6
// blocks/SM, regs capped by launch_bounds(256,5) -> 5/SM min; 148*5=740 >= 640;
// pattern validated on-HW by the R7 fused kernel at 42KB/640 blocks)
__device__ __forceinline__ void grid_sync() {
    __syncthreads();
    if (threadIdx.x == 0) {
        unsigned gen = *(volatile unsigned*)&g_gen;
        __threadfence();
        if (atomicAdd(&g_arrive, 1u) == GRID - 1u) {
            g_arrive = 0;
            __threadfence();
            *(volatile unsigned*)&g_gen = gen + 1u;
        } else {
            while (*(volatile unsigned*)&g_gen == gen) { __nanosleep(64); }
        }
        __threadfence();
    }
    __syncthreads();
}

// Decode one row's candidates given precomputed exp values.
__device__ __forceinline__ void emit_cands(
    int row, int lane, float e0, float e1, float e2, float inv,
    const float* __restrict__ reg, const float* __restrict__ props) {
    float p0 = props[row*4+0], p1 = props[row*4+1];
    float p2 = props[row*4+2], p3 = props[row*4+3];
    float w = p2 - p0, h = p3 - p1;
    float cx = p0 + 0.5f * w, cy = p1 + 0.5f * h;
    int b = row / NN, n = row % NN;

    #pragma unroll
    for (int u = 0; u < 3; u++) {
        int c = lane + u * 32;
        if (c == 0 || c >= CC) continue;
        float sc = (u == 0 ? e0 : (u == 1 ? e1 : e2)) * inv;
        if (sc > SCORE_TH) {
            const float* r = reg + (size_t)row * (CC*4) + c*4;
            float dx = r[0] * 0.1f, dy = r[1] * 0.1f;
            float dw = fminf(r[2] * 0.2f, CLIPV);
            float dh = fminf(r[3] * 0.2f, CLIPV);
            float pcx = dx * w + cx, pcy = dy * h + cy;
            float pw = expf(dw) * w, ph = expf(dh) * h;
            float x0 = fminf(fmaxf(pcx - 0.5f * pw, 0.f), IMG_W);
            float y0 = fminf(fmaxf(pcy - 0.5f * ph, 0.f), IMG_H);
            float x1 = fminf(fmaxf(pcx + 0.5f * pw, 0.f), IMG_W);
            float y1 = fminf(fmaxf(pcy + 0.5f * ph, 0.f), IMG_H);
            int prob = b * FG + (c - 1);
            int slot = atomicAdd(&g_cnt[prob], 1);
            int base = prob * NN + slot;
            g_score[base] = sc;
            g_box[base*4+0] = x0; g_box[base*4+1] = y0;
            g_box[base*4+2] = x1; g_box[base*4+3] = y1;
            g_nidx[base] = (unsigned)n;
        }
    }
}

// Fused: phase 1 softmax+decode (warp = 2 rows), grid barrier,
// phase 2 per-(image,class) sort + greedy NMS + compaction.
__global__ void __launch_bounds__(THR, 5)
k_sm_nms(const float* __restrict__ logits, const float* __restrict__ reg,
         const float* __restrict__ props) {
    __shared__ unsigned long long skey[1024];
    __shared__ int spay[1024];
    __shared__ float sx0[NN], sy0[NN], sx1[NN], sy1[NN], ssc[NN];
    __shared__ int skept[NN];
    int tid  = threadIdx.x;
    int lane = tid & 31;
    int gwarp = blockIdx.x * (THR/32) + (tid >> 5);   // 0..5119

    // ---- Phase 1: softmax + decode (row-pairs 0..3999) ----
    if (gwarp < BB*NN/2) {
        int rowA = gwarp * 2, rowB = rowA + 1;
        const float* lgA = logits + (size_t)rowA * CC;
        const float* lgB = logits + (size_t)rowB * CC;

        float a0 = lgA[lane], b0 = lgB[lane];
        float a1 = lgA[lane + 32], b1 = lgB[lane + 32];
        bool hi = (lane + 64 < CC);
        float a2 = hi ? lgA[lane + 64] : -3.402823466e38f;
        float b2 = hi ? lgB[lane + 64] : -3.402823466e38f;

        float mxA = fmaxf(fmaxf(a0, a1), a2);
        float mxB = fmaxf(fmaxf(b0, b1), b2);
        #pragma unroll
        for (int o = 16; o; o >>= 1) {
            mxA = fmaxf(mxA, __shfl_xor_sync(0xFFFFFFFFu, mxA, o));
            mxB = fmaxf(mxB, __shfl_xor_sync(0xFFFFFFFFu, mxB, o));
        }
        float eA0 = __expf(a0 - mxA), eB0 = __expf(b0 - mxB);
        float eA1 = __expf(a1 - mxA), eB1 = __expf(b1 - mxB);
        float eA2 = hi ? __expf(a2 - mxA) : 0.f;
        float eB2 = hi ? __expf(b2 - mxB) : 0.f;
        float sA = eA0 + eA1 + eA2, sB = eB0 + eB1 + eB2;
        #pragma unroll
        for (int o = 16; o; o >>= 1) {
            sA += __shfl_xor_sync(0xFFFFFFFFu, sA, o);
            sB += __shfl_xor_sync(0xFFFFFFFFu, sB, o);
        }
        emit_cands(rowA, lane, eA0, eA1, eA2, 1.0f / sA, reg, props);
        emit_cands(rowB, lane, eB0, eB1, eB2, 1.0f / sB, reg, props);
    }

    grid_sync();

    // ---- Phase 2: per-(image,class) sort + NMS ----
    int prob = blockIdx.x;
    int c = prob % FG;
    int m = g_cnt[prob];
    if (m > NN) m = NN;

    int n2 = 32; while (n2 < m) n2 <<= 1;   // <=1024

    for (int i = tid; i < n2; i += THR) {
        if (i < m) {
            float sc = g_score[prob*NN + i];
            unsigned nb = g_nidx[prob*NN + i];
            skey[i] = ((unsigned long long)__float_as_uint(sc) << 32)
                    | (unsigned long long)(0xFFFFFFFFu - nb);
            spay[i] = i;
        } else { skey[i] = 0ull; spay[i] = 0; }
    }
    __syncthreads();

    for (int k = 2; k <= n2; k <<= 1) {
        for (int j = k >> 1; j > 0; j >>= 1) {
            for (int i = tid; i < n2; i += THR) {
                int ix = i ^ j;
                if (ix > i) {
                    bool up = ((i & k) == 0);
                    unsigned long long a = skey[i], bk = skey[ix];
                    bool sw = up ? (a < bk) : (a > bk);
                    if (sw) {
                        skey[i] = bk; skey[ix] = a;
                        int t = spay[i]; spay[i] = spay[ix]; spay[ix] = t;
                    }
                }
            }
            __syncthreads();
        }
    }

    for (int i = tid; i < m; i += THR) {
        int p = prob*NN + spay[i];
        ssc[i] = __uint_as_float((unsigned)(skey[i] >> 32));
        sx0[i] = g_box[p*4+0]; sy0[i] = g_box[p*4+1];
        sx1[i] = g_box[p*4+2]; sy1[i] = g_box[p*4+3];
        skept[i] = 1;
    }
    __syncthreads();

    // greedy NMS: only surviving boxes suppress; forward only
    for (int i = 0; i < m; i++) {
        if (skept[i]) {
            float bx0 = sx0[i], by0 = sy0[i], bx1 = sx1[i], by1 = sy1[i];
            float a1 = (bx1 - bx0) * (by1 - by0);
            for (int j = i + 1 + tid; j < m; j += THR) {
                if (!skept[j]) continue;
                float lx = fmaxf(bx0, sx0[j]);
                float ly = fmaxf(by0, sy0[j]);
                float rx = fminf(bx1, sx1[j]);
                float ry = fminf(by1, sy1[j]);
                float iw = fmaxf(rx - lx, 0.f);
                float ih = fmaxf(ry - ly, 0.f);
                float inter = iw * ih;
                float a2 = (sx1[j] - sx0[j]) * (sy1[j] - sy0[j]);
                float iou = inter / (a1 + a2 - inter + 1e-9f);
                if (iou > NMS_TH) skept[j] = 0;
            }
        }
        __syncthreads();
    }

    for (int i = tid; i < m; i += THR) {
        int base = prob*NN + i;
        g_box[base*4+0] = sx0[i]; g_box[base*4+1] = sy0[i];
        g_box[base*4+2] = sx1[i]; g_box[base*4+3] = sy1[i];
        if (skept[i]) {
            int pos = atomicAdd(&g_kcnt[prob], 1);
            unsigned fl = (unsigned)(c * NN + i);
            g_keys[prob*NN + pos] =
                ((unsigned long long)__float_as_uint(ssc[i]) << 32)
              | (unsigned long long)(0xFFFFFFFFu - fl);
        }
    }
    if (tid == 0) g_cnt[prob] = 0;   // reset for next replay
}

__device__ __forceinline__ void bitonic_desc(unsigned long long* a, int n2, int tid, int nthr) {
    for (int k = 2; k <= n2; k <<= 1) {
        for (int j = k >> 1; j > 0; j >>= 1) {
            for (int i = tid; i < n2; i += nthr) {
                int ix = i ^ j;
                if (ix > i) {
                    bool up = ((i & k) == 0);
                    unsigned long long x = a[i], y = a[ix];
                    bool sw = up ? (x < y) : (x > y);
                    if (sw) { a[i] = y; a[ix] = x; }
                }
            }
            __syncthreads();
        }
    }
}

// Per image: radix-select top-100 over kept keys, emit boxes/scores/labels.
__global__ void k_topk(float* __restrict__ out) {
    int b = blockIdx.x;
    __shared__ unsigned long long keys[CAP];
    __shared__ unsigned long long cbuf[CB];
    __shared__ int hist[NB];
    __shared__ int scnt[FG];
    __shared__ int soff[FG + 1];
    __shared__ int sth, sccnt;
    int tid = threadIdx.x;
    int lane = tid & 31;
    int wid = tid >> 5;           // 32 warps @ 1024 threads

    if (tid < FG) {
        int p = b * FG + tid;
        scnt[tid] = min(g_kcnt[p], NN);
        g_kcnt[p] = 0;            // reset for next replay
    }
    if (tid == 0) { sth = -1; sccnt = 0; }
    hist[tid] = 0;
    __syncthreads();
    if (tid == 0) {
        int acc = 0;
        for (int c2 = 0; c2 < FG; c2++) { soff[c2] = acc; acc += scnt[c2]; }
        soff[FG] = acc;
    }
    __syncthreads();
    int L = soff[FG]; if (L > CAP) L = CAP;

    for (int c2 = wid; c2 < FG; c2 += 32) {
        int off = soff[c2], cnt = scnt[c2];
        const unsigned long long* src = g_keys + (size_t)(b * FG + c2) * NN;
        for (int i = lane; i < cnt; i += 32) {
            int d = off + i;
            if (d < CAP) keys[d] = src[i];
        }
    }
    __syncthreads();

    for (int i = tid; i < L; i += blockDim.x) {
        int bin = (int)(keys[i] >> 48) - BIN_BASE;
        bin = max(0, min(NB - 1, bin));
        atomicAdd(&hist[bin], 1);
    }
    __syncthreads();

    #pragma unroll
    for (int d = 1; d < NB; d <<= 1) {
        int v = (tid + d < NB) ? hist[tid + d] : 0;
        __syncthreads();
        hist[tid] += v;
        __syncthreads();
    }

    if (hist[tid] >= KK && (tid == NB - 1 || hist[tid + 1] < KK)) sth = tid;
    __syncthreads();

    int t = sth;
    bool fast = (t >= 0) && (hist[t] <= CB);

    const unsigned long long* srt;
    if (fast) {
        for (int i = tid; i < L; i += blockDim.x) {
            int bin = (int)(keys[i] >> 48) - BIN_BASE;
            bin = max(0, min(NB - 1, bin));
            if (bin >= t) {
                int pos = atomicAdd(&sccnt, 1);
                cbuf[pos] = keys[i];
            }
        }
        __syncthreads();
        int cnum = sccnt;
        int n2 = 128; while (n2 < cnum) n2 <<= 1;
        for (int i = cnum + tid; i < n2; i += blockDim.x) cbuf[i] = 0ull;
        __syncthreads();
        bitonic_desc(cbuf, n2, tid, blockDim.x);
        srt = cbuf;
    } else {
        int n2 = 128; while (n2 < L) n2 <<= 1;
        for (int i = L + tid; i < n2; i += blockDim.x) keys[i] = 0ull;
        __syncthreads();
        bitonic_desc(keys, n2, tid, blockDim.x);
        srt = keys;
    }

    if (tid < KK) {
        unsigned long long key = srt[tid];
        float sc = __uint_as_float((unsigned)(key >> 32));
        float x0 = 0.f, y0 = 0.f, x1 = 0.f, y1 = 0.f, scw = 0.f;
        int label = 0;
        if (sc > 0.0f) {
            unsigned fl = 0xFFFFFFFFu - (unsigned)(key & 0xFFFFFFFFull);
            int c2 = (int)(fl / NN), i = (int)(fl % NN);
            int base = (b * FG + c2) * NN + i;
            x0 = g_box[base*4+0]; y0 = g_box[base*4+1];
            x1 = g_box[base*4+2]; y1 = g_box[base*4+3];
            scw = sc; label = c2 + 1;
        }
        int bk = b * KK + tid;
        out[bk*4+0] = x0; out[bk*4+1] = y0; out[bk*4+2] = x1; out[bk*4+3] = y1;
        out[BB*KK*4 + bk] = scw;                  // top_s at 3200
        out[BB*KK*4 + BB*KK + bk] = (float)label; // labels at 4000
        g_labels[bk] = label;
    }
}

// sigmoid via HW tanh (1 MUFU).
__device__ __forceinline__ float fast_sigmoid(float x) {
    float t;
    asm("tanh.approx.f32 %0, %1;" : "=f"(t) : "f"(x * 0.5f));
    return fmaf(t, 0.5f, 0.5f);
}

// Per detection: gather class channel of mask logits, sigmoid.
// R8-measured config: 2 float4/thread, 307 blocks.
__global__ void k_mask(const float* __restrict__ ml, float* __restrict__ out) {
    const int TOT4 = BB*KK*(MSZ*MSZ/4);       // 156800 float4
    float* mout = out + (BB*KK*4 + 2*BB*KK);
    int idx0 = (blockIdx.x * blockDim.x + threadIdx.x) * 2;

    #pragma unroll
    for (int u = 0; u < 2; u++) {
        int idx = idx0 + u;
        if (idx >= TOT4) break;
        int bk = idx / (MSZ*MSZ/4);
        int t4 = idx % (MSZ*MSZ/4);
        int label = g_labels[bk];
        const float4* src = (const float4*)(ml + ((size_t)bk * CC + (size_t)label) * (MSZ*MSZ));
        float4 v = src[t4];
        v.x = fast_sigmoid(v.x);
        v.y = fast_sigmoid(v.y);
        v.z = fast_sigmoid(v.z);
        v.w = fast_sigmoid(v.w);
        ((float4*)(mout + (size_t)bk * (MSZ*MSZ)))[t4] = v;
    }
}

extern "C" void kernel_launch(void* const* d_in, const int* in_sizes, int n_in,
                              void* d_out, int out_size) {
    (void)in_sizes; (void)n_in; (void)out_size;
    const float* logits = (const float*)d_in[0];
    const float* reg    = (const float*)d_in[1];
    const float* props  = (const float*)d_in[2];
    const float* ml     = (const float*)d_in[3];
    float* out = (float*)d_out;

    k_sm_nms<<<GRID, THR>>>(logits, reg, props);
    k_topk<<<BB, 1024>>>(out);
    const int TOT4 = BB*KK*(MSZ*MSZ/4);
    k_mask<<<(TOT4/2 + 255) / 256, 256>>>(ml, out);
}

// round 15
// speedup vs baseline: 1.2194x; 1.2194x over previous
#include <cuda_runtime.h>
#include <math.h>

#define BB 8
#define NN 1000
#define CC 81
#define FG 80           // foreground classes
#define KK 100
#define MSZ 28
#define NPROB (BB*FG)   // 640
#define IMG_W 1216.0f
#define IMG_H 800.0f
#define SCORE_TH 0.05f
#define NMS_TH 0.5f
#define CLIPV 4.135166556742356f   // log(1000/16)
#define CAP 4096
#define NB 1024         // select histogram bins
#define CB 512          // collect buffer cap
#define BIN_BASE 0x3D4C // float bits top-16 of 0.05
#define FULLM 0xFFFFFFFFu

// ---- scratch (no allocations allowed) ----
__device__ int                g_cnt[NPROB];          // candidates per (b,c)
__device__ int                g_kcnt[NPROB];         // kept after NMS per (b,c)
__device__ float              g_score[NPROB*NN];
__device__ float              g_box[NPROB*NN*4];
__device__ unsigned           g_nidx[NPROB*NN];
__device__ unsigned long long g_keys[NPROB*NN];      // compacted kept keys
__device__ int                g_labels[BB*KK];

// Decode one row's candidates given precomputed exp values.
__device__ __forceinline__ void emit_cands(
    int row, int lane, float e0, float e1, float e2, float inv,
    const float* __restrict__ reg, const float* __restrict__ props) {
    float p0 = props[row*4+0], p1 = props[row*4+1];
    float p2 = props[row*4+2], p3 = props[row*4+3];
    float w = p2 - p0, h = p3 - p1;
    float cx = p0 + 0.5f * w, cy = p1 + 0.5f * h;
    int b = row / NN, n = row % NN;

    #pragma unroll
    for (int u = 0; u < 3; u++) {
        int c = lane + u * 32;
        if (c == 0 || c >= CC) continue;
        float sc = (u == 0 ? e0 : (u == 1 ? e1 : e2)) * inv;
        if (sc > SCORE_TH) {
            const float* r = reg + (size_t)row * (CC*4) + c*4;
            float dx = r[0] * 0.1f, dy = r[1] * 0.1f;
            float dw = fminf(r[2] * 0.2f, CLIPV);
            float dh = fminf(r[3] * 0.2f, CLIPV);
            float pcx = dx * w + cx, pcy = dy * h + cy;
            float pw = expf(dw) * w, ph = expf(dh) * h;
            float x0 = fminf(fmaxf(pcx - 0.5f * pw, 0.f), IMG_W);
            float y0 = fminf(fmaxf(pcy - 0.5f * ph, 0.f), IMG_H);
            float x1 = fminf(fmaxf(pcx + 0.5f * pw, 0.f), IMG_W);
            float y1 = fminf(fmaxf(pcy + 0.5f * ph, 0.f), IMG_H);
            int prob = b * FG + (c - 1);
            int slot = atomicAdd(&g_cnt[prob], 1);
            int base = prob * NN + slot;
            g_score[base] = sc;
            g_box[base*4+0] = x0; g_box[base*4+1] = y0;
            g_box[base*4+2] = x1; g_box[base*4+3] = y1;
            g_nidx[base] = (unsigned)n;
        }
    }
}

// One warp per TWO proposal rows.
__global__ void k_softmax_cand(const float* __restrict__ logits,
                               const float* __restrict__ reg,
                               const float* __restrict__ props) {
    int warp = (blockIdx.x * blockDim.x + threadIdx.x) >> 5;
    int lane = threadIdx.x & 31;
    int rowA = warp * 2;
    int rowB = rowA + 1;
    if (rowA >= BB * NN) return;
    const float* lgA = logits + (size_t)rowA * CC;
    const float* lgB = logits + (size_t)rowB * CC;

    float a0 = lgA[lane], b0 = lgB[lane];
    float a1 = lgA[lane + 32], b1 = lgB[lane + 32];
    bool hi = (lane + 64 < CC);
    float a2 = hi ? lgA[lane + 64] : -3.402823466e38f;
    float b2 = hi ? lgB[lane + 64] : -3.402823466e38f;

    float mxA = fmaxf(fmaxf(a0, a1), a2);
    float mxB = fmaxf(fmaxf(b0, b1), b2);
    #pragma unroll
    for (int o = 16; o; o >>= 1) {
        mxA = fmaxf(mxA, __shfl_xor_sync(FULLM, mxA, o));
        mxB = fmaxf(mxB, __shfl_xor_sync(FULLM, mxB, o));
    }
    float eA0 = __expf(a0 - mxA), eB0 = __expf(b0 - mxB);
    float eA1 = __expf(a1 - mxA), eB1 = __expf(b1 - mxB);
    float eA2 = hi ? __expf(a2 - mxA) : 0.f;
    float eB2 = hi ? __expf(b2 - mxB) : 0.f;
    float sA = eA0 + eA1 + eA2, sB = eB0 + eB1 + eB2;
    #pragma unroll
    for (int o = 16; o; o >>= 1) {
        sA += __shfl_xor_sync(FULLM, sA, o);
        sB += __shfl_xor_sync(FULLM, sB, o);
    }
    emit_cands(rowA, lane, eA0, eA1, eA2, 1.0f / sA, reg, props);
    emit_cands(rowB, lane, eB0, eB1, eB2, 1.0f / sB, reg, props);
}

struct NmsFast {
    unsigned long long karr[64];
    unsigned long long ksort[64];
    float4 sbx[64];
};
struct NmsSlow {
    unsigned long long skey[1024];
    int   spay[1024];
    float sx0[NN], sy0[NN], sx1[NN], sy1[NN], ssc[NN];
    int   skept[NN];
};
union NmsSmem { NmsFast f; NmsSlow s; };

// Per (image,class): sort by (score desc, proposal idx asc), greedy NMS,
// write sorted boxes + compacted kept keys. Fast path (m<=64): single warp,
// zero block barriers. Slow path (m>64): original smem bitonic+loop.
__global__ void k_nms() {
    int prob = blockIdx.x;
    int c = prob % FG;
    int m = g_cnt[prob];
    if (m > NN) m = NN;
    __shared__ NmsSmem sm;
    int tid = threadIdx.x;
    const int NT = 128;

    if (m <= 64) {
        // ---------- FAST PATH: warp 0 only, no __syncthreads ----------
        if (tid < 32) {
            int l = tid;
            // build keys (score desc, proposal idx asc)
            if (l < m) {
                sm.f.karr[l] = ((unsigned long long)__float_as_uint(g_score[prob*NN + l]) << 32)
                             | (unsigned long long)(FULLM - g_nidx[prob*NN + l]);
            }
            if (l + 32 < m) {
                sm.f.karr[l+32] = ((unsigned long long)__float_as_uint(g_score[prob*NN + l + 32]) << 32)
                                | (unsigned long long)(FULLM - g_nidx[prob*NN + l + 32]);
            }
            __syncwarp();
            // rank-sort (keys unique -> ranks unique)
            unsigned long long k0 = (l < m)      ? sm.f.karr[l]    : 0ull;
            unsigned long long k1 = (l + 32 < m) ? sm.f.karr[l+32] : 0ull;
            int r0 = 0, r1 = 0;
            for (int j = 0; j < m; j++) {
                unsigned long long kj = sm.f.karr[j];
                r0 += (kj > k0);
                r1 += (kj > k1);
            }
            __syncwarp();
            const float4* gb4 = (const float4*)g_box;
            if (l < m) {
                sm.f.ksort[r0] = k0;
                sm.f.sbx[r0] = gb4[prob*NN + l];
            }
            if (l + 32 < m) {
                sm.f.ksort[r1] = k1;
                sm.f.sbx[r1] = gb4[prob*NN + l + 32];
            }
            __syncwarp();
            // lane l now owns sorted positions l and l+32
            float4 b0 = sm.f.sbx[l];
            float4 b1 = sm.f.sbx[l+32];
            bool kept0 = (l < m);
            bool kept1 = (l + 32 < m);
            // greedy NMS: kept boxes suppress forward only
            for (int i = 0; i < m; i++) {
                unsigned lo = __ballot_sync(FULLM, kept0);
                unsigned hiM = __ballot_sync(FULLM, kept1);
                bool iskept = (i < 32) ? ((lo >> i) & 1u) : ((hiM >> (i - 32)) & 1u);
                if (iskept) {
                    float4 bi = sm.f.sbx[i];
                    float a1 = (bi.z - bi.x) * (bi.w - bi.y);
                    if (kept0 && l > i) {
                        float lx = fmaxf(bi.x, b0.x), ly = fmaxf(bi.y, b0.y);
                        float rx = fminf(bi.z, b0.z), ry = fminf(bi.w, b0.w);
                        float inter = fmaxf(rx - lx, 0.f) * fmaxf(ry - ly, 0.f);
                        float a2 = (b0.z - b0.x) * (b0.w - b0.y);
                        if (inter / (a1 + a2 - inter + 1e-9f) > NMS_TH) kept0 = false;
                    }
                    if (kept1) {   // l+32 > i always when bit i kept and i <= 63
                        float lx = fmaxf(bi.x, b1.x), ly = fmaxf(bi.y, b1.y);
                        float rx = fminf(bi.z, b1.z), ry = fminf(bi.w, b1.w);
                        float inter = fmaxf(rx - lx, 0.f) * fmaxf(ry - ly, 0.f);
                        float a2 = (b1.z - b1.x) * (b1.w - b1.y);
                        if ((l + 32 > i) && inter / (a1 + a2 - inter + 1e-9f) > NMS_TH) kept1 = false;
                    }
                }
            }
            unsigned lo = __ballot_sync(FULLM, kept0);
            unsigned hiM = __ballot_sync(FULLM, kept1);
            // write sorted boxes (topk dereferences by sorted position)
            float4* gb4w = (float4*)g_box;
            if (l < m)      gb4w[prob*NN + l]      = b0;
            if (l + 32 < m) gb4w[prob*NN + l + 32] = b1;
            // compact kept keys deterministically via popc prefix
            if (kept0) {
                int pos = __popc(lo & ((1u << l) - 1u));
                g_keys[prob*NN + pos] =
                    (sm.f.ksort[l] & 0xFFFFFFFF00000000ull)
                  | (unsigned long long)(FULLM - (unsigned)(c * NN + l));
            }
            if (kept1) {
                int pos = __popc(lo) + __popc(hiM & ((1u << l) - 1u));
                g_keys[prob*NN + pos] =
                    (sm.f.ksort[l+32] & 0xFFFFFFFF00000000ull)
                  | (unsigned long long)(FULLM - (unsigned)(c * NN + l + 32));
            }
            if (l == 0) {
                g_kcnt[prob] = __popc(lo) + __popc(hiM);
                g_cnt[prob] = 0;   // reset for next replay
            }
        }
        return;
    }

    // ---------- SLOW PATH (m > 64): original block algorithm ----------
    int n2 = 128; while (n2 < m) n2 <<= 1;   // <=1024

    for (int i = tid; i < n2; i += NT) {
        if (i < m) {
            float sc = g_score[prob*NN + i];
            unsigned nb = g_nidx[prob*NN + i];
            sm.s.skey[i] = ((unsigned long long)__float_as_uint(sc) << 32)
                         | (unsigned long long)(FULLM - nb);
            sm.s.spay[i] = i;
        } else { sm.s.skey[i] = 0ull; sm.s.spay[i] = 0; }
    }
    __syncthreads();

    for (int k = 2; k <= n2; k <<= 1) {
        for (int j = k >> 1; j > 0; j >>= 1) {
            for (int i = tid; i < n2; i += NT) {
                int ix = i ^ j;
                if (ix > i) {
                    bool up = ((i & k) == 0);
                    unsigned long long a = sm.s.skey[i], bk = sm.s.skey[ix];
                    bool sw = up ? (a < bk) : (a > bk);
                    if (sw) {
                        sm.s.skey[i] = bk; sm.s.skey[ix] = a;
                        int t = sm.s.spay[i]; sm.s.spay[i] = sm.s.spay[ix]; sm.s.spay[ix] = t;
                    }
                }
            }
            __syncthreads();
        }
    }

    for (int i = tid; i < m; i += NT) {
        int p = prob*NN + sm.s.spay[i];
        sm.s.ssc[i] = __uint_as_float((unsigned)(sm.s.skey[i] >> 32));
        sm.s.sx0[i] = g_box[p*4+0]; sm.s.sy0[i] = g_box[p*4+1];
        sm.s.sx1[i] = g_box[p*4+2]; sm.s.sy1[i] = g_box[p*4+3];
        sm.s.skept[i] = 1;
    }
    __syncthreads();

    for (int i = 0; i < m; i++) {
        if (sm.s.skept[i]) {
            float bx0 = sm.s.sx0[i], by0 = sm.s.sy0[i];
            float bx1 = sm.s.sx1[i], by1 = sm.s.sy1[i];
            float a1 = (bx1 - bx0) * (by1 - by0);
            for (int j = i + 1 + tid; j < m; j += NT) {
                if (!sm.s.skept[j]) continue;
                float lx = fmaxf(bx0, sm.s.sx0[j]);
                float ly = fmaxf(by0, sm.s.sy0[j]);
                float rx = fminf(bx1, sm.s.sx1[j]);
                float ry = fminf(by1, sm.s.sy1[j]);
                float inter = fmaxf(rx - lx, 0.f) * fmaxf(ry - ly, 0.f);
                float a2 = (sm.s.sx1[j] - sm.s.sx0[j]) * (sm.s.sy1[j] - sm.s.sy0[j]);
                if (inter / (a1 + a2 - inter + 1e-9f) > NMS_TH) sm.s.skept[j] = 0;
            }
        }
        __syncthreads();
    }

    for (int i = tid; i < m; i += NT) {
        int base = prob*NN + i;
        g_box[base*4+0] = sm.s.sx0[i]; g_box[base*4+1] = sm.s.sy0[i];
        g_box[base*4+2] = sm.s.sx1[i]; g_box[base*4+3] = sm.s.sy1[i];
        if (sm.s.skept[i]) {
            int pos = atomicAdd(&g_kcnt[prob], 1);
            g_keys[prob*NN + pos] =
                ((unsigned long long)__float_as_uint(sm.s.ssc[i]) << 32)
              | (unsigned long long)(FULLM - (unsigned)(c * NN + i));
        }
    }
    if (tid == 0) g_cnt[prob] = 0;   // reset for next replay
}

__device__ __forceinline__ void bitonic_desc(unsigned long long* a, int n2, int tid, int nthr) {
    for (int k = 2; k <= n2; k <<= 1) {
        for (int j = k >> 1; j > 0; j >>= 1) {
            for (int i = tid; i < n2; i += nthr) {
                int ix = i ^ j;
                if (ix > i) {
                    bool up = ((i & k) == 0);
                    unsigned long long x = a[i], y = a[ix];
                    bool sw = up ? (x < y) : (x > y);
                    if (sw) { a[i] = y; a[ix] = x; }
                }
            }
            __syncthreads();
        }
    }
}

// Per image: radix-select top ~K by score high-bits (hierarchical-scan
// threshold), rank-sort the selected set, emit top-100.
__global__ void k_topk(float* __restrict__ out) {
    int b = blockIdx.x;
    __shared__ unsigned long long keys[CAP];
    __shared__ unsigned long long cbuf[CB];
    __shared__ int hist[NB];
    __shared__ int scnt[FG];
    __shared__ int soff[FG + 1];
    __shared__ int wsum[32], wsuf[32];
    __shared__ int sth, sccnt;
    int tid = threadIdx.x;
    int lane = tid & 31;
    int wid = tid >> 5;           // 32 warps @ 1024 threads

    if (tid < FG) {
        int p = b * FG + tid;
        scnt[tid] = min(g_kcnt[p], NN);
        g_kcnt[p] = 0;            // reset for next replay
    }
    if (tid == 0) { sth = -1; sccnt = 0; }
    hist[tid] = 0;
    __syncthreads();
    if (tid == 0) {
        int acc = 0;
        for (int c2 = 0; c2 < FG; c2++) { soff[c2] = acc; acc += scnt[c2]; }
        soff[FG] = acc;
    }
    __syncthreads();
    int L = soff[FG]; if (L > CAP) L = CAP;

    for (int c2 = wid; c2 < FG; c2 += 32) {
        int off = soff[c2], cnt = scnt[c2];
        const unsigned long long* src = g_keys + (size_t)(b * FG + c2) * NN;
        for (int i = lane; i < cnt; i += 32) {
            int d = off + i;
            if (d < CAP) keys[d] = src[i];
        }
    }
    __syncthreads();

    // histogram on score top-16 bits
    for (int i = tid; i < L; i += blockDim.x) {
        int bin = (int)(keys[i] >> 48) - BIN_BASE;
        bin = max(0, min(NB - 1, bin));
        atomicAdd(&hist[bin], 1);
    }
    __syncthreads();

    // suffix sum via hierarchical warp scan (3 barriers):
    // hist[i] := # elements in bins >= i
    {
        int v = hist[tid];
        #pragma unroll
        for (int off = 1; off < 32; off <<= 1) {
            int t2 = __shfl_down_sync(FULLM, v, off);
            if (lane + off < 32) v += t2;
        }
        if (lane == 0) wsum[wid] = v;     // warp total (suffix at lane 0)
        __syncthreads();
        if (wid == 0) {
            int s = wsum[lane];
            #pragma unroll
            for (int off = 1; off < 32; off <<= 1) {
                int t2 = __shfl_down_sync(FULLM, s, off);
                if (lane + off < 32) s += t2;
            }
            wsuf[lane] = s - wsum[lane];  // sum of warps strictly after
        }
        __syncthreads();
        hist[tid] = v + wsuf[wid];
        __syncthreads();
    }

    // threshold bin: largest t with suffix(t) >= K
    if (hist[tid] >= KK && (tid == NB - 1 || hist[tid + 1] < KK)) sth = tid;
    __syncthreads();

    int t = sth;
    bool fast = (t >= 0) && (hist[t] <= CB);

    const unsigned long long* srt;
    if (fast) {
        for (int i = tid; i < L; i += blockDim.x) {
            int bin = (int)(keys[i] >> 48) - BIN_BASE;
            bin = max(0, min(NB - 1, bin));
            if (bin >= t) {
                int pos = atomicAdd(&sccnt, 1);
                cbuf[pos] = keys[i];
            }
        }
        __syncthreads();
        int cnum = sccnt;                 // >= K by construction, <= CB
        // rank-sort: unique keys, one element per thread, broadcast reads
        if (tid < cnum) {
            unsigned long long key = cbuf[tid];
            int r = 0;
            for (int j = 0; j < cnum; j++) r += (cbuf[j] > key);
            keys[r] = key;
        }
        __syncthreads();
        srt = keys;
    } else {
        int n2 = 128; while (n2 < L) n2 <<= 1;
        for (int i = L + tid; i < n2; i += blockDim.x) keys[i] = 0ull;
        __syncthreads();
        bitonic_desc(keys, n2, tid, blockDim.x);
        srt = keys;
    }

    if (tid < KK) {
        unsigned long long key = srt[tid];
        float sc = __uint_as_float((unsigned)(key >> 32));
        float x0 = 0.f, y0 = 0.f, x1 = 0.f, y1 = 0.f, scw = 0.f;
        int label = 0;
        if (sc > 0.0f) {
            unsigned fl = FULLM - (unsigned)(key & 0xFFFFFFFFull);
            int c2 = (int)(fl / NN), i = (int)(fl % NN);
            int base = (b * FG + c2) * NN + i;
            x0 = g_box[base*4+0]; y0 = g_box[base*4+1];
            x1 = g_box[base*4+2]; y1 = g_box[base*4+3];
            scw = sc; label = c2 + 1;
        }
        int bk = b * KK + tid;
        out[bk*4+0] = x0; out[bk*4+1] = y0; out[bk*4+2] = x1; out[bk*4+3] = y1;
        out[BB*KK*4 + bk] = scw;                  // top_s at 3200
        out[BB*KK*4 + BB*KK + bk] = (float)label; // labels at 4000
        g_labels[bk] = label;
    }
}

// sigmoid via HW tanh (1 MUFU).
__device__ __forceinline__ float fast_sigmoid(float x) {
    float t;
    asm("tanh.approx.f32 %0, %1;" : "=f"(t) : "f"(x * 0.5f));
    return fmaf(t, 0.5f, 0.5f);
}

// Per detection: gather class channel of mask logits, sigmoid.
// R8-measured config: 2 float4/thread, 307 blocks.
__global__ void k_mask(const float* __restrict__ ml, float* __restrict__ out) {
    const int TOT4 = BB*KK*(MSZ*MSZ/4);       // 156800 float4
    float* mout = out + (BB*KK*4 + 2*BB*KK);
    int idx0 = (blockIdx.x * blockDim.x + threadIdx.x) * 2;

    #pragma unroll
    for (int u = 0; u < 2; u++) {
        int idx = idx0 + u;
        if (idx >= TOT4) break;
        int bk = idx / (MSZ*MSZ/4);
        int t4 = idx % (MSZ*MSZ/4);
        int label = g_labels[bk];
        const float4* src = (const float4*)(ml + ((size_t)bk * CC + (size_t)label) * (MSZ*MSZ));
        float4 v = src[t4];
        v.x = fast_sigmoid(v.x);
        v.y = fast_sigmoid(v.y);
        v.z = fast_sigmoid(v.z);
        v.w = fast_sigmoid(v.w);
        ((float4*)(mout + (size_t)bk * (MSZ*MSZ)))[t4] = v;
    }
}

extern "C" void kernel_launch(void* const* d_in, const int* in_sizes, int n_in,
                              void* d_out, int out_size) {
    (void)in_sizes; (void)n_in; (void)out_size;
    const float* logits = (const float*)d_in[0];
    const float* reg    = (const float*)d_in[1];
    const float* props  = (const float*)d_in[2];
    const float* ml     = (const float*)d_in[3];
    float* out = (float*)d_out;

    k_softmax_cand<<<(BB*NN/2 + 7) / 8, 256>>>(logits, reg, props);
    k_nms<<<NPROB, 128>>>();
    k_topk<<<BB, 1024>>>(out);
    const int TOT4 = BB*KK*(MSZ*MSZ/4);
    k_mask<<<(TOT4/2 + 255) / 256, 256>>>(ml, out);
}